// round 14
// baseline (speedup 1.0000x reference)
#include <cuda_runtime.h>
#include <cuda_bf16.h>
#include <cstdint>

#define BATCH   4096
#define INF     8192
#define OUTF    8192
#define NGRP    1024
#define WLEN    (NGRP * INF)

#define NBLK    256                 // 2 CTAs/SM x 148 SMs = 296 >= 256: co-resident guaranteed
#define NCB     8                   // column blocks of 256 float4
#define NCHUNK  (NBLK / NCB)        // 32 row chunks
#define RPC     (BATCH / NCHUNK)    // 128 rows per chunk

// Scratch (allocation-free rule: __device__ globals)
__device__ float g_partial[NCHUNK * INF];   // 1 MB
__device__ float g_val[INF];                // 32 KB column means
__device__ unsigned int g_bar1;             // monotonic, never reset
__device__ unsigned int g_bar2;             // monotonic, never reset

// ---------------------------------------------------------------------------
// Single persistent kernel, 256 blocks x 256 threads (2 CTAs/SM -> all
// co-resident on 148 SMs; spin barriers cannot deadlock). Device-wide sync via
// monotonically increasing counters: the generation is derived from the value
// itself (old >> log2(arrivals)), so no reset is needed across graph replays.
// ---------------------------------------------------------------------------
__global__ void __launch_bounds__(256) fused_all_kernel(
    const float* __restrict__ x,
    float*       __restrict__ out,
    const float* __restrict__ wflat,
    const float* __restrict__ mins,
    const float* __restrict__ maxs,
    const int*   __restrict__ start_pos,
    const int*   __restrict__ offsets,
    const int*   __restrict__ sizes,
    const int*   __restrict__ mask)
{
    const int tid = threadIdx.x;
    const int bid = blockIdx.x;                 // 0..255
    const int cb  = bid & (NCB - 1);            // 0..7  column block
    const int rc  = bid >> 3;                   // 0..31 row chunk
    const int c4  = cb * 256 + tid;             // 0..2047
    const size_t row_stride4 = INF / 4;         // 2048

    // ===================== Phase 1: zero-fill + partial sums ================
    {
        const float4 z = {0.f, 0.f, 0.f, 0.f};
        // 8M float4 / 256 blocks = 32768 per block = 128 per thread
        float4* __restrict__ o4 =
            reinterpret_cast<float4*>(out) + (size_t)bid * 32768 + tid;

        const float4* __restrict__ xp =
            reinterpret_cast<const float4*>(x) + (size_t)rc * RPC * row_stride4 + c4;

        float4 a0 = {0.f,0.f,0.f,0.f};
        float4 a1 = {0.f,0.f,0.f,0.f};
        float4 a2 = {0.f,0.f,0.f,0.f};
        float4 a3 = {0.f,0.f,0.f,0.f};

        for (int it = 0; it < RPC / 8; it++) {   // 16 iterations
            const int r = it * 8;
            // 8 fire-and-forget zero stores co-issued with the 8 loads
            #pragma unroll
            for (int i = 0; i < 8; i++)
                o4[(size_t)(it * 8 + i) * 256] = z;

            float4 v0 = xp[(size_t)(r + 0) * row_stride4];
            float4 v1 = xp[(size_t)(r + 1) * row_stride4];
            float4 v2 = xp[(size_t)(r + 2) * row_stride4];
            float4 v3 = xp[(size_t)(r + 3) * row_stride4];
            float4 v4 = xp[(size_t)(r + 4) * row_stride4];
            float4 v5 = xp[(size_t)(r + 5) * row_stride4];
            float4 v6 = xp[(size_t)(r + 6) * row_stride4];
            float4 v7 = xp[(size_t)(r + 7) * row_stride4];
            a0.x += v0.x; a0.y += v0.y; a0.z += v0.z; a0.w += v0.w;
            a1.x += v1.x; a1.y += v1.y; a1.z += v1.z; a1.w += v1.w;
            a2.x += v2.x; a2.y += v2.y; a2.z += v2.z; a2.w += v2.w;
            a3.x += v3.x; a3.y += v3.y; a3.z += v3.z; a3.w += v3.w;
            a0.x += v4.x; a0.y += v4.y; a0.z += v4.z; a0.w += v4.w;
            a1.x += v5.x; a1.y += v5.y; a1.z += v5.z; a1.w += v5.w;
            a2.x += v6.x; a2.y += v6.y; a2.z += v6.z; a2.w += v6.w;
            a3.x += v7.x; a3.y += v7.y; a3.z += v7.z; a3.w += v7.w;
        }
        float4 ps;
        ps.x = (a0.x + a1.x) + (a2.x + a3.x);
        ps.y = (a0.y + a1.y) + (a2.y + a3.y);
        ps.z = (a0.z + a1.z) + (a2.z + a3.z);
        ps.w = (a0.w + a1.w) + (a2.w + a3.w);
        reinterpret_cast<float4*>(g_partial)[(size_t)rc * row_stride4 + c4] = ps;
    }

    // ===================== Barrier 1 (256 arrivals, shift 8) ================
    __threadfence();
    if (tid == 0) {
        const unsigned old = atomicAdd(&g_bar1, 1u);
        if (bid < 32) {
            const unsigned target = ((old >> 8) + 1u) << 8;
            volatile unsigned* p = &g_bar1;
            while (*p < target) { __nanosleep(64); }
            __threadfence();
        }
    }
    if (bid >= 32) return;          // block-uniform exit; they already arrived
    __syncthreads();

    // ===================== Phase 2: reduce partials -> val (32 blocks) ======
    {
        const int j = bid * 256 + tid;   // 0..8191
        float s0 = 0.f, s1 = 0.f, s2 = 0.f, s3 = 0.f;
        #pragma unroll
        for (int k = 0; k < NCHUNK; k += 4) {
            s0 += g_partial[(size_t)(k + 0) * INF + j];
            s1 += g_partial[(size_t)(k + 1) * INF + j];
            s2 += g_partial[(size_t)(k + 2) * INF + j];
            s3 += g_partial[(size_t)(k + 3) * INF + j];
        }
        g_val[j] = ((s0 + s1) + (s2 + s3)) * (1.0f / (float)BATCH);
    }

    // ===================== Barrier 2 (32 arrivals, shift 5) =================
    __threadfence();
    if (tid == 0) {
        const unsigned old = atomicAdd(&g_bar2, 1u);
        if (bid == 0) {
            const unsigned target = ((old >> 5) + 1u) << 5;
            volatile unsigned* p = &g_bar2;
            while (*p < target) { __nanosleep(64); }
            __threadfence();
        }
    }
    if (bid != 0) return;           // block-uniform exit
    __syncthreads();

    // ===================== Phase 3: scalar + masked row 0 (block 0) =========
    __shared__ float smins[NGRP];
    __shared__ float red[256];

    #pragma unroll
    for (int c = 0; c < NGRP / 256; c++)
        smins[c * 256 + tid] = mins[c * 256 + tid];
    __syncthreads();

    float acc = 0.f;
    #pragma unroll
    for (int c = 0; c < INF / 256; c++) {   // 32 columns per thread
        const int j = c * 256 + tid;
        const float val = g_val[j];

        // searchsorted(mins, val, side='right') - 1
        int lo = 0, hi = NGRP;
        while (lo < hi) {
            int mid = (lo + hi) >> 1;
            if (smins[mid] <= val) lo = mid + 1; else hi = mid;
        }
        const int g  = lo - 1;
        const int gc = min(max(g, 0), NGRP - 1);
        const bool hit = (g >= 0) && (val >= smins[gc]) && (val <= maxs[gc]);
        const int pos = j - start_pos[gc];
        const bool pos_ok = (pos >= 0) && (pos < sizes[gc]);

        float w = 0.f;
        if (hit && pos_ok) {
            long long idx = (long long)offsets[gc] + (long long)pos;
            idx = idx < 0 ? 0 : idx;
            idx = idx > (long long)(WLEN - 1) ? (long long)(WLEN - 1) : idx;
            w = wflat[idx];
        }
        acc += val * w;
    }

    red[tid] = acc;
    __syncthreads();
    #pragma unroll
    for (int sft = 128; sft > 0; sft >>= 1) {
        if (tid < sft) red[tid] += red[tid + sft];
        __syncthreads();
    }
    const float s = red[0];   // valid in all threads after last __syncthreads

    // Masked row 0: 2048 float4 groups, 8 per thread.
    #pragma unroll
    for (int c = 0; c < OUTF / 4 / 256; c++) {
        const int i4 = c * 256 + tid;
        const int j = i4 * 4;
        float4 v;
        v.x = (mask[j + 0] != 0) ? s : 0.f;
        v.y = (mask[j + 1] != 0) ? s : 0.f;
        v.z = (mask[j + 2] != 0) ? s : 0.f;
        v.w = (mask[j + 3] != 0) ? s : 0.f;
        reinterpret_cast<float4*>(out)[i4] = v;
    }
}

// ---------------------------------------------------------------------------
extern "C" void kernel_launch(void* const* d_in, const int* in_sizes, int n_in,
                              void* d_out, int out_size)
{
    const float* x         = (const float*)d_in[0];
    const float* wflat     = (const float*)d_in[1];
    const float* mins      = (const float*)d_in[2];
    const float* maxs      = (const float*)d_in[3];
    const int*   start_pos = (const int*)d_in[4];
    const int*   offsets   = (const int*)d_in[5];
    const int*   sizes     = (const int*)d_in[6];
    const int*   out_mask  = (const int*)d_in[7];
    float*       out       = (float*)d_out;

    fused_all_kernel<<<NBLK, 256>>>(x, out, wflat, mins, maxs,
                                    start_pos, offsets, sizes, out_mask);
}

// round 15
// speedup vs baseline: 1.4227x; 1.4227x over previous
#include <cuda_runtime.h>
#include <cuda_bf16.h>
#include <cstdint>

#define BATCH   4096
#define INF     8192
#define OUTF    8192
#define NGRP    1024
#define WLEN    (NGRP * INF)

#define NBLK    256                 // 2 CTAs/SM x 148 SMs = 296 >= 256: co-resident
#define NTHR    1024                // big blocks -> 262K threads total
#define NCB     2                   // column blocks of 1024 float4
#define NCHUNK  (NBLK / NCB)        // 128 row chunks
#define RPC     (BATCH / NCHUNK)    // 32 rows per chunk

// Scratch (allocation-free rule: __device__ globals)
__device__ float g_partial[NCHUNK * INF];   // 4 MB
__device__ float g_val[INF];                // 32 KB column means
__device__ unsigned int g_bar1;             // monotonic, never reset
__device__ unsigned int g_bar2;             // monotonic, never reset

// ---------------------------------------------------------------------------
// Single persistent kernel, 256 blocks x 1024 threads (2 CTAs/SM co-resident,
// 262K threads for DRAM saturation; spin barriers cannot deadlock).
// Device-wide sync via monotonically increasing counters: the generation is
// derived from the counter value (old >> log2(arrivals)), so no reset is
// needed across graph replays and the kernel stays deterministic.
// ---------------------------------------------------------------------------
__global__ void __launch_bounds__(NTHR) fused_all_kernel(
    const float* __restrict__ x,
    float*       __restrict__ out,
    const float* __restrict__ wflat,
    const float* __restrict__ mins,
    const float* __restrict__ maxs,
    const int*   __restrict__ start_pos,
    const int*   __restrict__ offsets,
    const int*   __restrict__ sizes,
    const int*   __restrict__ mask)
{
    const int tid = threadIdx.x;
    const int bid = blockIdx.x;                 // 0..255
    const int cb  = bid & (NCB - 1);            // 0..1  column block
    const int rc  = bid >> 1;                   // 0..127 row chunk
    const int c4  = cb * NTHR + tid;            // 0..2047
    const size_t row_stride4 = INF / 4;         // 2048

    // ===================== Phase 1: zero-fill + partial sums ================
    {
        const float4 z = {0.f, 0.f, 0.f, 0.f};
        // 8M float4 / 256 blocks = 32768 per block = 32 per thread
        float4* __restrict__ o4 =
            reinterpret_cast<float4*>(out) + (size_t)bid * 32768 + tid;

        const float4* __restrict__ xp =
            reinterpret_cast<const float4*>(x) + (size_t)rc * RPC * row_stride4 + c4;

        float4 a0 = {0.f,0.f,0.f,0.f};
        float4 a1 = {0.f,0.f,0.f,0.f};
        float4 a2 = {0.f,0.f,0.f,0.f};
        float4 a3 = {0.f,0.f,0.f,0.f};

        #pragma unroll
        for (int it = 0; it < RPC / 8; it++) {   // 4 iterations
            const int r = it * 8;
            // 8 fire-and-forget zero stores co-issued with the 8 loads
            #pragma unroll
            for (int i = 0; i < 8; i++)
                o4[(size_t)(it * 8 + i) * NTHR] = z;

            float4 v0 = xp[(size_t)(r + 0) * row_stride4];
            float4 v1 = xp[(size_t)(r + 1) * row_stride4];
            float4 v2 = xp[(size_t)(r + 2) * row_stride4];
            float4 v3 = xp[(size_t)(r + 3) * row_stride4];
            float4 v4 = xp[(size_t)(r + 4) * row_stride4];
            float4 v5 = xp[(size_t)(r + 5) * row_stride4];
            float4 v6 = xp[(size_t)(r + 6) * row_stride4];
            float4 v7 = xp[(size_t)(r + 7) * row_stride4];
            a0.x += v0.x; a0.y += v0.y; a0.z += v0.z; a0.w += v0.w;
            a1.x += v1.x; a1.y += v1.y; a1.z += v1.z; a1.w += v1.w;
            a2.x += v2.x; a2.y += v2.y; a2.z += v2.z; a2.w += v2.w;
            a3.x += v3.x; a3.y += v3.y; a3.z += v3.z; a3.w += v3.w;
            a0.x += v4.x; a0.y += v4.y; a0.z += v4.z; a0.w += v4.w;
            a1.x += v5.x; a1.y += v5.y; a1.z += v5.z; a1.w += v5.w;
            a2.x += v6.x; a2.y += v6.y; a2.z += v6.z; a2.w += v6.w;
            a3.x += v7.x; a3.y += v7.y; a3.z += v7.z; a3.w += v7.w;
        }
        float4 ps;
        ps.x = (a0.x + a1.x) + (a2.x + a3.x);
        ps.y = (a0.y + a1.y) + (a2.y + a3.y);
        ps.z = (a0.z + a1.z) + (a2.z + a3.z);
        ps.w = (a0.w + a1.w) + (a2.w + a3.w);
        reinterpret_cast<float4*>(g_partial)[(size_t)rc * row_stride4 + c4] = ps;
    }

    // ===================== Barrier 1 (256 arrivals, shift 8) ================
    __threadfence();
    if (tid == 0) {
        const unsigned old = atomicAdd(&g_bar1, 1u);
        if (bid < 8) {
            const unsigned target = ((old >> 8) + 1u) << 8;
            volatile unsigned* p = &g_bar1;
            while (*p < target) { __nanosleep(64); }
            __threadfence();
        }
    }
    if (bid >= 8) return;           // block-uniform exit; they already arrived
    __syncthreads();

    // ===================== Phase 2: reduce partials -> val (8 blocks) =======
    {
        const int j = bid * NTHR + tid;   // 0..8191
        float s0 = 0.f, s1 = 0.f, s2 = 0.f, s3 = 0.f;
        #pragma unroll 8
        for (int k = 0; k < NCHUNK; k += 4) {
            s0 += g_partial[(size_t)(k + 0) * INF + j];
            s1 += g_partial[(size_t)(k + 1) * INF + j];
            s2 += g_partial[(size_t)(k + 2) * INF + j];
            s3 += g_partial[(size_t)(k + 3) * INF + j];
        }
        g_val[j] = ((s0 + s1) + (s2 + s3)) * (1.0f / (float)BATCH);
    }

    // ===================== Barrier 2 (8 arrivals, shift 3) ==================
    __threadfence();
    if (tid == 0) {
        const unsigned old = atomicAdd(&g_bar2, 1u);
        if (bid == 0) {
            const unsigned target = ((old >> 3) + 1u) << 3;
            volatile unsigned* p = &g_bar2;
            while (*p < target) { __nanosleep(64); }
            __threadfence();
        }
    }
    if (bid != 0) return;           // block-uniform exit
    __syncthreads();

    // ===================== Phase 3: scalar + masked row 0 (block 0) =========
    __shared__ float smins[NGRP];
    __shared__ float red[NTHR];

    smins[tid] = (tid < NGRP) ? mins[tid] : 0.f;   // NGRP == NTHR == 1024
    __syncthreads();

    float acc = 0.f;
    #pragma unroll
    for (int c = 0; c < INF / NTHR; c++) {   // 8 columns per thread
        const int j = c * NTHR + tid;
        const float val = g_val[j];

        // searchsorted(mins, val, side='right') - 1
        int lo = 0, hi = NGRP;
        while (lo < hi) {
            int mid = (lo + hi) >> 1;
            if (smins[mid] <= val) lo = mid + 1; else hi = mid;
        }
        const int g  = lo - 1;
        const int gc = min(max(g, 0), NGRP - 1);
        const bool hit = (g >= 0) && (val >= smins[gc]) && (val <= maxs[gc]);
        const int pos = j - start_pos[gc];
        const bool pos_ok = (pos >= 0) && (pos < sizes[gc]);

        float w = 0.f;
        if (hit && pos_ok) {
            long long idx = (long long)offsets[gc] + (long long)pos;
            idx = idx < 0 ? 0 : idx;
            idx = idx > (long long)(WLEN - 1) ? (long long)(WLEN - 1) : idx;
            w = wflat[idx];
        }
        acc += val * w;
    }

    red[tid] = acc;
    __syncthreads();
    #pragma unroll
    for (int sft = NTHR / 2; sft > 0; sft >>= 1) {
        if (tid < sft) red[tid] += red[tid + sft];
        __syncthreads();
    }
    const float s = red[0];   // valid in all threads after last __syncthreads

    // Masked row 0: 2048 float4 groups, 2 per thread.
    #pragma unroll
    for (int c = 0; c < OUTF / 4 / NTHR; c++) {
        const int i4 = c * NTHR + tid;
        const int j = i4 * 4;
        float4 v;
        v.x = (mask[j + 0] != 0) ? s : 0.f;
        v.y = (mask[j + 1] != 0) ? s : 0.f;
        v.z = (mask[j + 2] != 0) ? s : 0.f;
        v.w = (mask[j + 3] != 0) ? s : 0.f;
        reinterpret_cast<float4*>(out)[i4] = v;
    }
}

// ---------------------------------------------------------------------------
extern "C" void kernel_launch(void* const* d_in, const int* in_sizes, int n_in,
                              void* d_out, int out_size)
{
    const float* x         = (const float*)d_in[0];
    const float* wflat     = (const float*)d_in[1];
    const float* mins      = (const float*)d_in[2];
    const float* maxs      = (const float*)d_in[3];
    const int*   start_pos = (const int*)d_in[4];
    const int*   offsets   = (const int*)d_in[5];
    const int*   sizes     = (const int*)d_in[6];
    const int*   out_mask  = (const int*)d_in[7];
    float*       out       = (float*)d_out;

    fused_all_kernel<<<NBLK, NTHR>>>(x, out, wflat, mins, maxs,
                                     start_pos, offsets, sizes, out_mask);
}

// round 17
// speedup vs baseline: 1.4313x; 1.0060x over previous
#include <cuda_runtime.h>
#include <cuda_bf16.h>
#include <cstdint>

#define BATCH   4096
#define INF     8192
#define OUTF    8192
#define NGRP    1024
#define WLEN    (NGRP * INF)

#define NB      148                 // one CTA per SM: co-residency unconditional
#define NTHR    1024

// Scratch (allocation-free rule: __device__ globals)
__device__ float g_partial[NB * INF];       // 148 x 8192 floats = 4.85 MB
__device__ float g_val[INF];                // 32 KB column means
__device__ unsigned int g_bar1;             // monotonic, never reset
__device__ unsigned int g_bar2;             // monotonic, never reset

// ---------------------------------------------------------------------------
// Single persistent kernel: 148 blocks x 1024 threads = exactly 1 CTA/SM.
// Residency is guaranteed by construction (148 blocks always fit in wave 1,
// independent of register count), so the spin barriers cannot deadlock --
// unlike R13/R16 where residency depended on ptxas's register allocation.
// At 1 CTA/SM each thread has the full 64 registers, so 4 float4 loads stay
// in flight per thread (32 warps/SM x 2KB = 64KB in-flight per SM >> the
// ~25KB needed to saturate DRAM).
// Device-wide sync via monotonically increasing counters: the generation is
// derived from the value itself (old / arrivals), so no reset is needed
// across graph replays and the kernel stays deterministic.
// ---------------------------------------------------------------------------
__global__ void __launch_bounds__(NTHR) fused_all_kernel(
    const float* __restrict__ x,
    float*       __restrict__ out,
    const float* __restrict__ wflat,
    const float* __restrict__ mins,
    const float* __restrict__ maxs,
    const int*   __restrict__ start_pos,
    const int*   __restrict__ offsets,
    const int*   __restrict__ sizes,
    const int*   __restrict__ mask)
{
    const int tid = threadIdx.x;
    const int bid = blockIdx.x;                 // 0..147

    // ===================== Phase 1: zero-fill + partial sums ================
    {
        // Contiguous row slab for this block: ~27-28 rows.
        const int r0 = (bid * BATCH) / NB;
        const int r1 = ((bid + 1) * BATCH) / NB;
        const int cA = tid;                     // float4 column 0..1023
        const int cB = tid + NTHR;              // float4 column 1024..2047
        const float4* __restrict__ xp = reinterpret_cast<const float4*>(x);

        // Grid-stride zero-fill state: 8M float4 over 151552 threads (~55.4 ea)
        const float4 z = {0.f, 0.f, 0.f, 0.f};
        float4* __restrict__ o4 = reinterpret_cast<float4*>(out);
        const size_t zstride = (size_t)NB * NTHR;           // 151552
        const size_t ztot    = (size_t)BATCH * OUTF / 4;    // 8388608
        size_t zi = (size_t)bid * NTHR + tid;

        float4 aA0 = {0.f,0.f,0.f,0.f};
        float4 aB0 = {0.f,0.f,0.f,0.f};
        float4 aA1 = {0.f,0.f,0.f,0.f};
        float4 aB1 = {0.f,0.f,0.f,0.f};

        int r = r0;
        for (; r + 2 <= r1; r += 2) {
            // 2 fire-and-forget zero stores interleaved with the 4 loads
            if (zi < ztot) { o4[zi] = z; zi += zstride; }
            if (zi < ztot) { o4[zi] = z; zi += zstride; }

            float4 vA0 = xp[(size_t)(r + 0) * 2048 + cA];
            float4 vB0 = xp[(size_t)(r + 0) * 2048 + cB];
            float4 vA1 = xp[(size_t)(r + 1) * 2048 + cA];
            float4 vB1 = xp[(size_t)(r + 1) * 2048 + cB];
            aA0.x += vA0.x; aA0.y += vA0.y; aA0.z += vA0.z; aA0.w += vA0.w;
            aB0.x += vB0.x; aB0.y += vB0.y; aB0.z += vB0.z; aB0.w += vB0.w;
            aA1.x += vA1.x; aA1.y += vA1.y; aA1.z += vA1.z; aA1.w += vA1.w;
            aB1.x += vB1.x; aB1.y += vB1.y; aB1.z += vB1.z; aB1.w += vB1.w;
        }
        if (r < r1) {   // odd-row tail
            float4 vA0 = xp[(size_t)r * 2048 + cA];
            float4 vB0 = xp[(size_t)r * 2048 + cB];
            aA0.x += vA0.x; aA0.y += vA0.y; aA0.z += vA0.z; aA0.w += vA0.w;
            aB0.x += vB0.x; aB0.y += vB0.y; aB0.z += vB0.z; aB0.w += vB0.w;
        }
        // zero-fill cleanup (at most ~2 extra stores)
        while (zi < ztot) { o4[zi] = z; zi += zstride; }

        float4 pA, pB;
        pA.x = aA0.x + aA1.x; pA.y = aA0.y + aA1.y;
        pA.z = aA0.z + aA1.z; pA.w = aA0.w + aA1.w;
        pB.x = aB0.x + aB1.x; pB.y = aB0.y + aB1.y;
        pB.z = aB0.z + aB1.z; pB.w = aB0.w + aB1.w;
        float4* __restrict__ gp4 = reinterpret_cast<float4*>(g_partial);
        gp4[(size_t)bid * 2048 + cA] = pA;
        gp4[(size_t)bid * 2048 + cB] = pB;
    }

    // ===================== Barrier 1 (148 arrivals) =========================
    __threadfence();
    __syncthreads();                 // all threads' stores published before arrive
    if (tid == 0) {
        const unsigned old = atomicAdd(&g_bar1, 1u);
        if (bid < 8) {
            const unsigned target = ((old / NB) + 1u) * NB;
            volatile unsigned* p = &g_bar1;
            while (*p < target) { __nanosleep(64); }
            __threadfence();
        }
    }
    if (bid >= 8) return;            // block-uniform exit; they already arrived
    __syncthreads();

    // ===================== Phase 2: reduce partials -> val (8 blocks) =======
    {
        const int j = bid * NTHR + tid;   // 0..8191
        float s0 = 0.f, s1 = 0.f, s2 = 0.f, s3 = 0.f;
        #pragma unroll 4
        for (int k = 0; k < NB; k += 4) {
            s0 += g_partial[(size_t)(k + 0) * INF + j];
            s1 += g_partial[(size_t)(k + 1) * INF + j];
            s2 += g_partial[(size_t)(k + 2) * INF + j];
            s3 += g_partial[(size_t)(k + 3) * INF + j];
        }
        g_val[j] = ((s0 + s1) + (s2 + s3)) * (1.0f / (float)BATCH);
    }

    // ===================== Barrier 2 (8 arrivals) ===========================
    __threadfence();
    __syncthreads();
    if (tid == 0) {
        const unsigned old = atomicAdd(&g_bar2, 1u);
        if (bid == 0) {
            const unsigned target = ((old >> 3) + 1u) << 3;
            volatile unsigned* p = &g_bar2;
            while (*p < target) { __nanosleep(64); }
            __threadfence();
        }
    }
    if (bid != 0) return;            // block-uniform exit
    __syncthreads();

    // ===================== Phase 3: scalar + masked row 0 (block 0) =========
    __shared__ float smins[NGRP];
    __shared__ float red[NTHR];

    smins[tid] = mins[tid];          // NGRP == NTHR == 1024
    __syncthreads();

    float acc = 0.f;
    #pragma unroll
    for (int c = 0; c < INF / NTHR; c++) {   // 8 columns per thread
        const int j = c * NTHR + tid;
        const float val = g_val[j];

        // searchsorted(mins, val, side='right') - 1
        int lo = 0, hi = NGRP;
        while (lo < hi) {
            int mid = (lo + hi) >> 1;
            if (smins[mid] <= val) lo = mid + 1; else hi = mid;
        }
        const int g  = lo - 1;
        const int gc = min(max(g, 0), NGRP - 1);
        const bool hit = (g >= 0) && (val >= smins[gc]) && (val <= maxs[gc]);
        const int pos = j - start_pos[gc];
        const bool pos_ok = (pos >= 0) && (pos < sizes[gc]);

        float w = 0.f;
        if (hit && pos_ok) {
            long long idx = (long long)offsets[gc] + (long long)pos;
            idx = idx < 0 ? 0 : idx;
            idx = idx > (long long)(WLEN - 1) ? (long long)(WLEN - 1) : idx;
            w = wflat[idx];
        }
        acc += val * w;
    }

    red[tid] = acc;
    __syncthreads();
    #pragma unroll
    for (int sft = NTHR / 2; sft > 0; sft >>= 1) {
        if (tid < sft) red[tid] += red[tid + sft];
        __syncthreads();
    }
    const float s = red[0];   // valid in all threads after last __syncthreads

    // Masked row 0: 2048 float4 groups, 2 per thread.
    #pragma unroll
    for (int c = 0; c < OUTF / 4 / NTHR; c++) {
        const int i4 = c * NTHR + tid;
        const int j = i4 * 4;
        float4 v;
        v.x = (mask[j + 0] != 0) ? s : 0.f;
        v.y = (mask[j + 1] != 0) ? s : 0.f;
        v.z = (mask[j + 2] != 0) ? s : 0.f;
        v.w = (mask[j + 3] != 0) ? s : 0.f;
        reinterpret_cast<float4*>(out)[i4] = v;
    }
}

// ---------------------------------------------------------------------------
extern "C" void kernel_launch(void* const* d_in, const int* in_sizes, int n_in,
                              void* d_out, int out_size)
{
    const float* x         = (const float*)d_in[0];
    const float* wflat     = (const float*)d_in[1];
    const float* mins      = (const float*)d_in[2];
    const float* maxs      = (const float*)d_in[3];
    const int*   start_pos = (const int*)d_in[4];
    const int*   offsets   = (const int*)d_in[5];
    const int*   sizes     = (const int*)d_in[6];
    const int*   out_mask  = (const int*)d_in[7];
    float*       out       = (float*)d_out;

    fused_all_kernel<<<NB, NTHR>>>(x, out, wflat, mins, maxs,
                                   start_pos, offsets, sizes, out_mask);
}